// round 1
// baseline (speedup 1.0000x reference)
#include <cuda_runtime.h>
#include <cstdint>

// ---------------------------------------------------------------------------
// SymmetricContraction: out[b,c] = sum_e y[b,e] * (
//       sum_{w,v,i} V3[c,e,w,v,i] x_w x_v x_i
//     + sum_{w,v}   V2[c,e,w,v]   x_w x_v
//     + sum_{w}     V1[c,e,w]     x_w )
// with V3[c,e,wvi] = sum_k U3[wvi,k] W3[e,k,c]   (V2, V1 analogous).
// E=10 < K3=23 makes the e-form 2.3x cheaper than the reference k-form.
// ---------------------------------------------------------------------------

namespace {
constexpr int LDIM = 16;
constexpr int EDIM = 10;
constexpr int CDIM = 256;
constexpr int BDIM = 1024;
constexpr int K3C  = 23;
constexpr int K2C  = 4;

constexpr int WV       = LDIM * LDIM;        // 256
constexpr int V3_PER_C = EDIM * WV * LDIM;   // 40960 floats
constexpr int V2_PER_C = EDIM * WV;          // 2560
constexpr int V1_PER_C = EDIM * LDIM;        // 160

// dynamic smem layout (bytes)
constexpr int SMEM_BYTES =
    V3_PER_C * 4 +        // 163840  V3[c] slice
    V2_PER_C * 4 +        //  10240  V2[c] slice
    V1_PER_C * 4 +        //    640  V1[c] slice
    128 * 17 * 8 +        //  17408  packed x pairs, padded stride 17
    128 * EDIM * 8 +      //  10240  packed y pairs
    8 * 256 * 4;          //   8192  reduction buffer
// total = 210560 < 227KB opt-in limit
}

// scratch (module-static device memory: allowed; no runtime allocation)
__device__ float V3g[CDIM * V3_PER_C];   // ~42 MB
__device__ float V2g[CDIM * V2_PER_C];
__device__ float V1g[CDIM * V1_PER_C];

// ---- packed f32x2 helpers (sm_103a) ---------------------------------------
__device__ __forceinline__ unsigned long long pk2(float a, float b) {
    unsigned long long r;
    asm("mov.b64 %0, {%1, %2};"
        : "=l"(r) : "r"(__float_as_uint(a)), "r"(__float_as_uint(b)));
    return r;
}
__device__ __forceinline__ unsigned long long fma2(unsigned long long a,
                                                   unsigned long long b,
                                                   unsigned long long c) {
    unsigned long long d;
    asm("fma.rn.f32x2 %0, %1, %2, %3;" : "=l"(d) : "l"(a), "l"(b), "l"(c));
    return d;
}
__device__ __forceinline__ unsigned long long mul2(unsigned long long a,
                                                   unsigned long long b) {
    unsigned long long d;
    asm("mul.rn.f32x2 %0, %1, %2;" : "=l"(d) : "l"(a), "l"(b));
    return d;
}
__device__ __forceinline__ void upk2(unsigned long long v, float& a, float& b) {
    unsigned int lo, hi;
    asm("mov.b64 {%0, %1}, %2;" : "=r"(lo), "=r"(hi) : "l"(v));
    a = __uint_as_float(lo);
    b = __uint_as_float(hi);
}

// ---- precompute kernels ----------------------------------------------------
// V3g[((c*E+e)*256+wv)*16+i] = sum_k U3[(wv*16+i)*23+k] * W3[(e*23+k)*256+c]
__global__ void k_v3(const float* __restrict__ U3, const float* __restrict__ W3) {
    const int o  = blockIdx.x * 256 + threadIdx.x;   // < 10,485,760
    const int i  = o & 15;
    const int t  = o >> 4;
    const int wv = t & 255;
    const int t2 = t >> 8;
    const int e  = t2 % EDIM;
    const int c  = t2 / EDIM;
    const float* u = U3 + (wv * 16 + i) * K3C;
    const float* w = W3 + (e * K3C) * CDIM + c;
    float s = 0.f;
#pragma unroll
    for (int k = 0; k < K3C; k++) s = fmaf(u[k], w[k * CDIM], s);
    V3g[o] = s;
}

__global__ void k_v2(const float* __restrict__ U2, const float* __restrict__ W2) {
    const int o  = blockIdx.x * 256 + threadIdx.x;   // < 655,360
    const int wv = o & 255;
    const int t2 = o >> 8;
    const int e  = t2 % EDIM;
    const int c  = t2 / EDIM;
    float s = 0.f;
#pragma unroll
    for (int k = 0; k < K2C; k++)
        s = fmaf(U2[wv * K2C + k], W2[(e * K2C + k) * CDIM + c], s);
    V2g[o] = s;
}

__global__ void k_v1(const float* __restrict__ U1, const float* __restrict__ W1) {
    const int o  = blockIdx.x * 256 + threadIdx.x;   // < 40,960
    const int w  = o & 15;
    const int t2 = o >> 4;
    const int e  = t2 % EDIM;
    const int c  = t2 / EDIM;
    V1g[o] = U1[w] * W1[e * CDIM + c];   // K1 == 1
}

// ---- main kernel -------------------------------------------------------------
// Grid: (c = 0..255, btile = 0..3). CTA: 512 threads, 1 c, 256 b's.
// Thread (tid): bg = tid & 63 owns b's {bg, bg+64, bg+128, bg+192} (two f32x2
// pairs); row-split r = tid >> 6 owns wv rows [32r, 32r+32) for every e.
__global__ __launch_bounds__(512, 1)
void sc_main(const float* __restrict__ x, const float* __restrict__ y,
             float* __restrict__ out) {
    extern __shared__ char smraw[];
    float* sV3 = reinterpret_cast<float*>(smraw);
    float* sV2 = sV3 + V3_PER_C;
    float* sV1 = sV2 + V2_PER_C;
    unsigned long long* sXp = reinterpret_cast<unsigned long long*>(sV1 + V1_PER_C);
    unsigned long long* sYp = sXp + 128 * 17;
    float* red = reinterpret_cast<float*>(sYp + 128 * EDIM);

    const int tid     = threadIdx.x;
    const int c       = blockIdx.x;
    const int btile   = blockIdx.y * 256;
    const int bg      = tid & 63;
    const int rowbase = (tid >> 6) * 32;

    // --- stage V slices (coalesced float4) ---
    {
        const float4* src = reinterpret_cast<const float4*>(V3g + c * V3_PER_C);
        float4* dst = reinterpret_cast<float4*>(sV3);
#pragma unroll
        for (int t = 0; t < 20; t++) dst[tid + t * 512] = src[tid + t * 512];

        const float4* s2 = reinterpret_cast<const float4*>(V2g + c * V2_PER_C);
        float4* d2 = reinterpret_cast<float4*>(sV2);
        for (int idx = tid; idx < V2_PER_C / 4; idx += 512) d2[idx] = s2[idx];

        if (tid < V1_PER_C) sV1[tid] = V1g[c * V1_PER_C + tid];
    }
    // --- stage packed x pairs: pair pb -> (b_lo, b_lo+64), b_lo = btile + (pb&63) + (pb>>6)*128
    for (int idx = tid; idx < 128 * 16; idx += 512) {
        const int pb  = idx >> 4;
        const int i   = idx & 15;
        const int blo = btile + (pb & 63) + ((pb >> 6) << 7);
        const float lo = x[(blo * CDIM + c) * LDIM + i];
        const float hi = x[((blo + 64) * CDIM + c) * LDIM + i];
        sXp[pb * 17 + i] = pk2(lo, hi);
    }
    // --- stage packed y pairs ---
    for (int idx = tid; idx < 128 * EDIM; idx += 512) {
        const int pb  = idx / EDIM;
        const int e   = idx - pb * EDIM;
        const int blo = btile + (pb & 63) + ((pb >> 6) << 7);
        sYp[pb * EDIM + e] = pk2(y[blo * EDIM + e], y[(blo + 64) * EDIM + e]);
    }
    __syncthreads();

    // x vectors for the i-dot live in registers (static unrolled indexing only)
    unsigned long long xp0[16], xp1[16];
#pragma unroll
    for (int i = 0; i < 16; i++) {
        xp0[i] = sXp[bg * 17 + i];
        xp1[i] = sXp[(bg + 64) * 17 + i];
    }

    unsigned long long acc0 = 0ull, acc1 = 0ull;

#pragma unroll 1
    for (int e = 0; e < EDIM; e++) {
        unsigned long long acce0 = 0ull, acce1 = 0ull;
        const float4* prow = reinterpret_cast<const float4*>(
            sV3 + e * (WV * LDIM) + rowbase * LDIM);
        const float* p2 = sV2 + e * WV + rowbase;
#pragma unroll 1
        for (int rr = 0; rr < 32; rr++) {
            const int wv = rowbase + rr;
            const int w  = wv >> 4;
            const int v  = wv & 15;
            const float4 a0 = prow[rr * 4 + 0];
            const float4 a1 = prow[rr * 4 + 1];
            const float4 a2 = prow[rr * 4 + 2];
            const float4 a3 = prow[rr * 4 + 3];
            const float v2v = p2[rr];
            const float av[16] = {a0.x, a0.y, a0.z, a0.w, a1.x, a1.y, a1.z, a1.w,
                                  a2.x, a2.y, a2.z, a2.w, a3.x, a3.y, a3.z, a3.w};
            // d = V2 + sum_i V3[..i] * x_i   (nu=2 folded as the dot's init)
            unsigned long long d0 = pk2(v2v, v2v);
            unsigned long long d1 = d0;
#pragma unroll
            for (int i = 0; i < 16; i++) {
                const unsigned long long t = pk2(av[i], av[i]);
                d0 = fma2(t, xp0[i], d0);
                d1 = fma2(t, xp1[i], d1);
            }
            const unsigned long long xwv0 = mul2(sXp[bg * 17 + w], sXp[bg * 17 + v]);
            const unsigned long long xwv1 =
                mul2(sXp[(bg + 64) * 17 + w], sXp[(bg + 64) * 17 + v]);
            acce0 = fma2(d0, xwv0, acce0);
            acce1 = fma2(d1, xwv1, acce1);
        }
        // nu=1 term, handled once (row-split 0 only; warp-uniform branch)
        if (rowbase == 0) {
#pragma unroll
            for (int w = 0; w < 16; w++) {
                const unsigned long long t = pk2(sV1[e * 16 + w], sV1[e * 16 + w]);
                acce0 = fma2(t, xp0[w], acce0);
                acce1 = fma2(t, xp1[w], acce1);
            }
        }
        // fold element weight y[b,e]
        const unsigned long long y0 = sYp[bg * EDIM + e];
        const unsigned long long y1 = sYp[(bg + 64) * EDIM + e];
        acc0 = fma2(y0, acce0, acc0);
        acc1 = fma2(y1, acce1, acc1);
    }

    // --- deterministic cross-split reduction ---
    float r0, r1, r2, r3;
    upk2(acc0, r0, r1);
    upk2(acc1, r2, r3);
    const int rsp = tid >> 6;
    red[rsp * 256 + bg]       = r0;
    red[rsp * 256 + bg + 64]  = r1;
    red[rsp * 256 + bg + 128] = r2;
    red[rsp * 256 + bg + 192] = r3;
    __syncthreads();
    if (tid < 256) {
        float s = 0.f;
#pragma unroll
        for (int k = 0; k < 8; k++) s += red[k * 256 + tid];
        out[(btile + tid) * CDIM + c] = s;
    }
}

// ---- launch -----------------------------------------------------------------
extern "C" void kernel_launch(void* const* d_in, const int* in_sizes, int n_in,
                              void* d_out, int out_size) {
    const float* x  = (const float*)d_in[0];
    const float* y  = (const float*)d_in[1];
    const float* U3 = (const float*)d_in[2];
    const float* U2 = (const float*)d_in[3];
    const float* U1 = (const float*)d_in[4];
    const float* W3 = (const float*)d_in[5];
    const float* W2 = (const float*)d_in[6];
    const float* W1 = (const float*)d_in[7];
    float* out = (float*)d_out;

    cudaFuncSetAttribute(sc_main, cudaFuncAttributeMaxDynamicSharedMemorySize,
                         SMEM_BYTES);

    k_v3<<<(CDIM * V3_PER_C) / 256, 256>>>(U3, W3);   // 40960 blocks
    k_v2<<<(CDIM * V2_PER_C) / 256, 256>>>(U2, W2);   //  2560 blocks
    k_v1<<<(CDIM * V1_PER_C) / 256, 256>>>(U1, W1);   //   160 blocks

    dim3 grid(CDIM, BDIM / 256);                      // (256, 4)
    sc_main<<<grid, 512, SMEM_BYTES>>>(x, y, out);
}

// round 2
// speedup vs baseline: 1.0934x; 1.0934x over previous
#include <cuda_runtime.h>
#include <cstdint>

// ---------------------------------------------------------------------------
// out[b,c] = sum_e y[b,e] * ( sum_{w,v,i} V3[c,e,w,v,i] x_w x_v x_i
//                           + sum_{w,v}   V2[c,e,w,v]   x_w x_v
//                           + sum_{w}     V1[c,e,w]     x_w )
// V3[c,e,wvi] = sum_k U3[wvi,k] W3[e,k,c]  (V2,V1 analogous), E=10 < K3=23.
//
// Round 2: i-packed f32x2 inner loop (no dup-movs), fixed LDG-bound k_v3.
// ---------------------------------------------------------------------------

namespace {
constexpr int LDIM = 16;
constexpr int EDIM = 10;
constexpr int CDIM = 256;
constexpr int BDIM = 1024;
constexpr int K3C  = 23;
constexpr int K2C  = 4;

constexpr int WV       = LDIM * LDIM;        // 256
constexpr int WVI      = WV * LDIM;          // 4096
constexpr int V3_PER_C = EDIM * WVI;         // 40960 floats
constexpr int V2_PER_C = EDIM * WV;          // 2560
constexpr int V1_PER_C = EDIM * LDIM;        // 160

// sc_main dynamic smem (bytes)
constexpr int SM_V3 = V3_PER_C * 4;          // 163840
constexpr int SM_XS = 256 * 17 * 4;          //  17408 scalar x, stride 17
constexpr int SM_YD = EDIM * 256 * 8;        //  20480 dup'd y pairs [e][b]
constexpr int SM_V2 = V2_PER_C * 4;          //  10240
constexpr int SM_RED = 4 * 256 * 4;          //   4096
constexpr int SMEM_MAIN = SM_V3 + SM_XS + SM_YD + SM_V2 + SM_RED;  // 216064

// k_v3 smem
constexpr int V3CHUNK_ROWS = 1024;
constexpr int SMEM_KV3 = V3CHUNK_ROWS * K3C * 4 + EDIM * K3C * 4 + 16; // ~95.2KB
}

__device__ float V3g[CDIM * V3_PER_C];   // ~42 MB scratch
__device__ float V2g[CDIM * V2_PER_C];
__device__ float V1g[CDIM * V1_PER_C];

// ---- packed f32x2 helpers (sm_103a) ----------------------------------------
using ull = unsigned long long;
__device__ __forceinline__ ull pk2(float a, float b) {
    ull r;
    asm("mov.b64 %0, {%1, %2};"
        : "=l"(r) : "r"(__float_as_uint(a)), "r"(__float_as_uint(b)));
    return r;
}
__device__ __forceinline__ ull fma2(ull a, ull b, ull c) {
    ull d;
    asm("fma.rn.f32x2 %0, %1, %2, %3;" : "=l"(d) : "l"(a), "l"(b), "l"(c));
    return d;
}
__device__ __forceinline__ void upk2(ull v, float& a, float& b) {
    unsigned int lo, hi;
    asm("mov.b64 {%0, %1}, %2;" : "=r"(lo), "=r"(hi) : "l"(v));
    a = __uint_as_float(lo);
    b = __uint_as_float(hi);
}

// ---- precompute: V3 ---------------------------------------------------------
// grid=256 (c), block=512. Stage U3 chunks coalesced; W3 column broadcast.
__global__ __launch_bounds__(512, 1)
void k_v3(const float* __restrict__ U3, const float* __restrict__ W3) {
    extern __shared__ float sm[];
    float* sU = sm;                       // [1024][23]
    float* sW = sm + V3CHUNK_ROWS * K3C;  // [10][23]

    const int tid = threadIdx.x;
    const int c   = blockIdx.x;

    if (tid < EDIM * K3C) {
        const int e = tid / K3C, k = tid - e * K3C;
        sW[tid] = W3[(e * K3C + k) * CDIM + c];
    }

    for (int chunk = 0; chunk < 4; chunk++) {
        __syncthreads();
        const float* gsrc = U3 + chunk * V3CHUNK_ROWS * K3C;
#pragma unroll
        for (int t = 0; t < 46; t++)      // 23552 / 512
            sU[tid + t * 512] = gsrc[tid + t * 512];
        __syncthreads();

        // two rows per thread, stride-512 apart (conflict-free LDS: stride 23)
        float u0[K3C], u1[K3C];
#pragma unroll
        for (int k = 0; k < K3C; k++) {
            u0[k] = sU[tid * K3C + k];
            u1[k] = sU[(tid + 512) * K3C + k];
        }
        const int r0 = chunk * V3CHUNK_ROWS + tid;
#pragma unroll 1
        for (int e = 0; e < EDIM; e++) {
            float s0 = 0.f, s1 = 0.f;
#pragma unroll
            for (int k = 0; k < K3C; k++) {
                const float w = sW[e * K3C + k];
                s0 = fmaf(u0[k], w, s0);
                s1 = fmaf(u1[k], w, s1);
            }
            float* dst = V3g + (c * EDIM + e) * WVI + r0;
            dst[0]   = s0;
            dst[512] = s1;
        }
    }
}

// ---- precompute: V2, V1 (tiny) ---------------------------------------------
__global__ void k_v2(const float* __restrict__ U2, const float* __restrict__ W2) {
    const int o  = blockIdx.x * 256 + threadIdx.x;
    const int wv = o & 255;
    const int t2 = o >> 8;
    const int e  = t2 % EDIM;
    const int c  = t2 / EDIM;
    float s = 0.f;
#pragma unroll
    for (int k = 0; k < K2C; k++)
        s = fmaf(U2[wv * K2C + k], W2[(e * K2C + k) * CDIM + c], s);
    V2g[o] = s;
}

__global__ void k_v1(const float* __restrict__ U1, const float* __restrict__ W1) {
    const int o  = blockIdx.x * 256 + threadIdx.x;   // 40960 total
    const int w  = o & 15;
    const int t2 = o >> 4;
    const int e  = t2 % EDIM;
    const int c  = t2 / EDIM;
    V1g[o] = U1[w] * W1[e * CDIM + c];
}

// ---- main kernel -------------------------------------------------------------
// grid (c=256, btile=4), 512 threads. bq = tid&127 owns b's {bq, bq+128};
// rsplit = tid>>7 owns 64 wv rows. Lanes of f32x2 carry (even-i, odd-i)
// partial sums; folded scalar at the end. nu2 rides in lane0 of d-init.
__global__ __launch_bounds__(512, 1)
void sc_main(const float* __restrict__ x, const float* __restrict__ y,
             float* __restrict__ out) {
    extern __shared__ char smraw[];
    float* sV3 = reinterpret_cast<float*>(smraw);
    float* sXs = sV3 + V3_PER_C;
    ull*   sYd = reinterpret_cast<ull*>(sXs + 256 * 17);
    float* sV2 = reinterpret_cast<float*>(sYd + EDIM * 256);
    float* red = sV2 + V2_PER_C;

    const int tid   = threadIdx.x;
    const int c     = blockIdx.x;
    const int base  = blockIdx.y * 256;     // btile start
    const int bq    = tid & 127;
    const int row0  = (tid >> 7) * 64;

    // ---- stage V3 slice (coalesced float4) ----
    {
        const float4* src = reinterpret_cast<const float4*>(V3g + c * V3_PER_C);
        float4* dst = reinterpret_cast<float4*>(sV3);
#pragma unroll
        for (int t = 0; t < 20; t++) dst[tid + t * 512] = src[tid + t * 512];

        const float4* s2 = reinterpret_cast<const float4*>(V2g + c * V2_PER_C);
        float4* d2 = reinterpret_cast<float4*>(sV2);
        for (int idx = tid; idx < V2_PER_C / 4; idx += 512) d2[idx] = s2[idx];
    }
    // ---- stage x scalars (stride 17) ----
#pragma unroll
    for (int t = 0; t < 8; t++) {
        const int idx = tid + t * 512;       // 4096 = 256 b * 16 i
        const int b = idx >> 4, i = idx & 15;
        sXs[b * 17 + i] = x[((base + b) * CDIM + c) * LDIM + i];
    }
    // ---- stage dup'd y pairs [e][b] ----
#pragma unroll
    for (int t = 0; t < 5; t++) {
        const int idx = tid + t * 512;       // 2560 = 10 e * 256 b
        const int b = idx & 255, e = idx >> 8;
        const float yv = y[(base + b) * EDIM + e];
        sYd[e * 256 + b] = pk2(yv, yv);
    }
    __syncthreads();

    // ---- per-thread i-packed x pairs ----
    ull xpA[8], xpB[8];
#pragma unroll
    for (int t = 0; t < 8; t++) {
        xpA[t] = pk2(sXs[bq * 17 + 2 * t], sXs[bq * 17 + 2 * t + 1]);
        xpB[t] = pk2(sXs[(bq + 128) * 17 + 2 * t], sXs[(bq + 128) * 17 + 2 * t + 1]);
    }

    ull accA = 0ull, accB = 0ull;

#pragma unroll 1
    for (int rr = 0; rr < 64; rr++) {
        const int wv = row0 + rr;
        const int w  = wv >> 4;
        const int v  = wv & 15;
        const float xwA = sXs[bq * 17 + w] * sXs[bq * 17 + v];
        const float xwB = sXs[(bq + 128) * 17 + w] * sXs[(bq + 128) * 17 + v];
        ull rA = 0ull, rB = 0ull;
#pragma unroll 2
        for (int e = 0; e < EDIM; e++) {
            const ulonglong2* prow = reinterpret_cast<const ulonglong2*>(
                sV3 + e * WVI + wv * 16);
            const ulonglong2 p0 = prow[0];
            const ulonglong2 p1 = prow[1];
            const ulonglong2 p2 = prow[2];
            const ulonglong2 p3 = prow[3];
            const ull dinit = pk2(sV2[e * WV + wv], 0.f);
            ull dA = fma2(p0.x, xpA[0], dinit);
            ull dB = fma2(p0.x, xpB[0], dinit);
            dA = fma2(p0.y, xpA[1], dA);  dB = fma2(p0.y, xpB[1], dB);
            dA = fma2(p1.x, xpA[2], dA);  dB = fma2(p1.x, xpB[2], dB);
            dA = fma2(p1.y, xpA[3], dA);  dB = fma2(p1.y, xpB[3], dB);
            dA = fma2(p2.x, xpA[4], dA);  dB = fma2(p2.x, xpB[4], dB);
            dA = fma2(p2.y, xpA[5], dA);  dB = fma2(p2.y, xpB[5], dB);
            dA = fma2(p3.x, xpA[6], dA);  dB = fma2(p3.x, xpB[6], dB);
            dA = fma2(p3.y, xpA[7], dA);  dB = fma2(p3.y, xpB[7], dB);
            rA = fma2(dA, sYd[e * 256 + bq], rA);
            rB = fma2(dB, sYd[e * 256 + bq + 128], rB);
        }
        accA = fma2(rA, pk2(xwA, xwA), accA);
        accB = fma2(rB, pk2(xwB, xwB), accB);
    }

    float a0, a1, b0, b1;
    upk2(accA, a0, a1);
    upk2(accB, b0, b1);
    float sA = a0 + a1, sB = b0 + b1;

    // ---- nu=1 term (rsplit 0 only; tiny, reads global V1g/y via L1) ----
    if (row0 == 0) {
        const float* v1 = V1g + c * V1_PER_C;
        float eA = 0.f, eB = 0.f;
#pragma unroll 1
        for (int e = 0; e < EDIM; e++) {
            float tA = 0.f, tB = 0.f;
#pragma unroll
            for (int w = 0; w < 16; w++) {
                const float vv = v1[e * 16 + w];
                tA = fmaf(vv, sXs[bq * 17 + w], tA);
                tB = fmaf(vv, sXs[(bq + 128) * 17 + w], tB);
            }
            eA = fmaf(y[(base + bq) * EDIM + e], tA, eA);
            eB = fmaf(y[(base + bq + 128) * EDIM + e], tB, eB);
        }
        sA += eA;
        sB += eB;
    }

    // ---- deterministic cross-split reduction ----
    const int rsp = tid >> 7;
    red[rsp * 256 + bq]       = sA;
    red[rsp * 256 + bq + 128] = sB;
    __syncthreads();
    if (tid < 256) {
        const float s = red[tid] + red[256 + tid] + red[512 + tid] + red[768 + tid];
        out[(base + tid) * CDIM + c] = s;
    }
}

// ---- launch -----------------------------------------------------------------
extern "C" void kernel_launch(void* const* d_in, const int* in_sizes, int n_in,
                              void* d_out, int out_size) {
    const float* x  = (const float*)d_in[0];
    const float* y  = (const float*)d_in[1];
    const float* U3 = (const float*)d_in[2];
    const float* U2 = (const float*)d_in[3];
    const float* U1 = (const float*)d_in[4];
    const float* W3 = (const float*)d_in[5];
    const float* W2 = (const float*)d_in[6];
    const float* W1 = (const float*)d_in[7];
    float* out = (float*)d_out;

    cudaFuncSetAttribute(k_v3, cudaFuncAttributeMaxDynamicSharedMemorySize,
                         SMEM_KV3);
    cudaFuncSetAttribute(sc_main, cudaFuncAttributeMaxDynamicSharedMemorySize,
                         SMEM_MAIN);

    k_v3<<<CDIM, 512, SMEM_KV3>>>(U3, W3);
    k_v2<<<(CDIM * V2_PER_C) / 256, 256>>>(U2, W2);
    k_v1<<<(CDIM * V1_PER_C) / 256, 256>>>(U1, W1);

    dim3 grid(CDIM, BDIM / 256);
    sc_main<<<grid, 512, SMEM_MAIN>>>(x, y, out);
}

// round 3
// speedup vs baseline: 2.5455x; 2.3281x over previous
#include <cuda_runtime.h>
#include <cstdint>

// ---------------------------------------------------------------------------
// out[b,c] = sum_e y[b,e]*( sum_{w<=v<=i} S3[c,e,(w,v,i)] x_w x_v x_i
//                         + sum_{w<=v}    S2[c,e,(w,v)]   x_w x_v
//                         + sum_w         V1[c,e,w]       x_w )
// S3 = symmetrized sum_k U3[perm(w,v,i),k] W3[e,k,c]  (816 vs 4096 terms).
// ---------------------------------------------------------------------------

namespace {
constexpr int LDIM = 16;
constexpr int EDIM = 10;
constexpr int CDIM = 256;
constexpr int BDIM = 1024;
constexpr int K3C  = 23;
constexpr int K2C  = 4;

constexpr int NPAIR   = 136;            // (w<=v) pairs
constexpr int NSLOT_U = 444;            // ull slots per (c,e) stream
constexpr int NSLOT_F = 888;            // floats per (c,e)
constexpr int S3_PER_C = EDIM * NSLOT_F;   // 8880 floats
constexpr int S2_PER_C = EDIM * NPAIR;     // 1360
constexpr int V1_PER_C = EDIM * LDIM;      // 160

// sc_main smem (bytes)
constexpr int SMEM_MAIN =
    S3_PER_C * 4 +      // 35520 S3 stream
    S2_PER_C * 4 +      //  5440
    256 * 17 * 4 +      // 17408 x scalars (stride 17)
    EDIM * 256 * 8 +    // 20480 dup'd y pairs [e][b]
    NPAIR * 3 * 4 +     //  1632 tables (w, v, off)
    8 * 256 * 4;        //  8192 reduction
// = 88672 bytes

constexpr int SMEM_KS3 = (NSLOT_F * K3C + EDIM * K3C + 8) * 4;  // ~82.7 KB
}

// ---- device scratch (static, no runtime alloc) ------------------------------
__device__ int   g_pw[NPAIR], g_pv[NPAIR], g_off[NPAIR];
__device__ int   g_s2p[NSLOT_F], g_s2i[NSLOT_F];     // slot -> pair, i (-1 = zero)
__device__ float U3symSg[NSLOT_F * K3C];             // [slot][k]
__device__ float S3g[CDIM * S3_PER_C];               // ~9.1 MB
__device__ float S2g[CDIM * S2_PER_C];
__device__ float V1g[CDIM * V1_PER_C];

// ---- packed f32x2 helpers (sm_103a) -----------------------------------------
using ull = unsigned long long;
__device__ __forceinline__ ull pk2(float a, float b) {
    ull r;
    asm("mov.b64 %0, {%1, %2};"
        : "=l"(r) : "r"(__float_as_uint(a)), "r"(__float_as_uint(b)));
    return r;
}
__device__ __forceinline__ ull fma2(ull a, ull b, ull c) {
    ull d;
    asm("fma.rn.f32x2 %0, %1, %2, %3;" : "=l"(d) : "l"(a), "l"(b), "l"(c));
    return d;
}
__device__ __forceinline__ void upk2(ull v, float& a, float& b) {
    unsigned int lo, hi;
    asm("mov.b64 {%0, %1}, %2;" : "=r"(lo), "=r"(hi) : "l"(v));
    a = __uint_as_float(lo);
    b = __uint_as_float(hi);
}

// ---- table builder (1 thread, trivial) ---------------------------------------
// Stream per (c,e): for each pair p=(w<=v): len8 = 8-(v>>1) ull slots.
// REVERSED i order: slot u holds floats for i = (14-2u, 15-2u); invalid (i<v) = 0.
__global__ void k_tab() {
    int p = 0, off = 0;
    for (int w = 0; w < LDIM; w++)
        for (int v = w; v < LDIM; v++) {
            g_pw[p] = w; g_pv[p] = v; g_off[p] = off;
            const int len8 = 8 - (v >> 1);
            for (int u = 0; u < len8; u++)
                for (int r = 0; r < 2; r++) {
                    const int s = 2 * (off + u) + r;
                    const int i = 14 - 2 * u + r;
                    g_s2p[s] = p;
                    g_s2i[s] = (i >= v) ? i : -1;
                }
            off += len8;
            p++;
        }
}

// ---- symmetrized U3: U3symSg[s][k] = sum over distinct perms of (w,v,i) -----
__device__ __forceinline__ float u3at(const float* U3, int a, int b, int c, int k) {
    return U3[((a * 16 + b) * 16 + c) * K3C + k];
}
__global__ void k_sym(const float* __restrict__ U3) {
    const int idx = blockIdx.x * 256 + threadIdx.x;
    if (idx >= NSLOT_F * K3C) return;
    const int k = idx % K3C;
    const int s = idx / K3C;
    const int i = g_s2i[s];
    float val = 0.f;
    if (i >= 0) {
        const int p = g_s2p[s];
        const int w = g_pw[p], v = g_pv[p];
        if (w == v && v == i) {
            val = u3at(U3, w, w, w, k);
        } else if (w == v) {         // w == v < i
            val = u3at(U3, w, w, i, k) + u3at(U3, w, i, w, k) + u3at(U3, i, w, w, k);
        } else if (v == i) {         // w < v == i
            val = u3at(U3, w, v, v, k) + u3at(U3, v, w, v, k) + u3at(U3, v, v, w, k);
        } else {                     // w < v < i
            val = u3at(U3, w, v, i, k) + u3at(U3, w, i, v, k) +
                  u3at(U3, v, w, i, k) + u3at(U3, v, i, w, k) +
                  u3at(U3, i, w, v, k) + u3at(U3, i, v, w, k);
        }
    }
    U3symSg[s * K3C + k] = val;
}

// ---- S3 per-c contraction: S3g[c][e][s] = sum_k U3symSg[s][k] W3[e,k,c] -----
__global__ __launch_bounds__(512, 1)
void k_s3(const float* __restrict__ W3) {
    extern __shared__ float sm[];
    float* sU = sm;                        // [888][23]
    float* sW = sm + NSLOT_F * K3C;        // [10][23]
    const int tid = threadIdx.x;
    const int c   = blockIdx.x;

    for (int t = tid; t < NSLOT_F * K3C; t += 512) sU[t] = U3symSg[t];
    if (tid < EDIM * K3C) {
        const int e = tid / K3C, k = tid - e * K3C;
        sW[tid] = W3[(e * K3C + k) * CDIM + c];
    }
    __syncthreads();

    for (int idx = tid; idx < S3_PER_C; idx += 512) {
        const int e = idx / NSLOT_F;
        const int s = idx - e * NSLOT_F;
        float a = 0.f;
#pragma unroll
        for (int k = 0; k < K3C; k++) a = fmaf(sU[s * K3C + k], sW[e * K3C + k], a);
        S3g[c * S3_PER_C + idx] = a;
    }
}

// ---- S2: symmetrized nu=2 ----------------------------------------------------
__global__ void k_s2(const float* __restrict__ U2, const float* __restrict__ W2) {
    const int idx = blockIdx.x * 256 + threadIdx.x;   // 256*1360
    if (idx >= CDIM * S2_PER_C) return;
    const int p = idx % NPAIR;
    const int e = (idx / NPAIR) % EDIM;
    const int c = idx / S2_PER_C;
    const int w = g_pw[p], v = g_pv[p];
    float s = 0.f;
#pragma unroll
    for (int k = 0; k < K2C; k++) {
        float u = U2[(w * 16 + v) * K2C + k];
        if (w != v) u += U2[(v * 16 + w) * K2C + k];
        s = fmaf(u, W2[(e * K2C + k) * CDIM + c], s);
    }
    S2g[c * S2_PER_C + e * NPAIR + p] = s;
}

// ---- V1 ----------------------------------------------------------------------
__global__ void k_v1(const float* __restrict__ U1, const float* __restrict__ W1) {
    const int o  = blockIdx.x * 256 + threadIdx.x;   // 40960
    const int w  = o & 15;
    const int t2 = o >> 4;
    const int e  = t2 % EDIM;
    const int c  = t2 / EDIM;
    V1g[o] = U1[w] * W1[e * CDIM + c];
}

// ---- main kernel: unrolled dot block ------------------------------------------
// slot u <-> i-pair q = 7-u; xp[q] = packed (x_{2q}, x_{2q+1}).
template <int N>
__device__ __forceinline__ void dot_block(
    const ull* __restrict__ sS3u, int off, const float* __restrict__ sS2,
    const ull* __restrict__ sYd, int p, int bg,
    const ull (&xp0)[8], const ull (&xp1)[8], const ull (&xp2)[8], const ull (&xp3)[8],
    ull& ya0, ull& ya1, ull& ya2, ull& ya3)
{
#pragma unroll 1
    for (int e = 0; e < EDIM; e++) {
        const ull* st = sS3u + e * NSLOT_U + off;
        const float s2 = sS2[e * NPAIR + p];
        ull d0 = pk2(s2, 0.f);
        ull d1 = d0, d2 = d0, d3 = d0;
#pragma unroll
        for (int u = N - 1; u >= 0; u--) {
            const ull t = st[u];
            d0 = fma2(t, xp0[7 - u], d0);
            d1 = fma2(t, xp1[7 - u], d1);
            d2 = fma2(t, xp2[7 - u], d2);
            d3 = fma2(t, xp3[7 - u], d3);
        }
        const ull* yrow = sYd + e * 256;
        ya0 = fma2(d0, yrow[bg], ya0);
        ya1 = fma2(d1, yrow[bg + 64], ya1);
        ya2 = fma2(d2, yrow[bg + 128], ya2);
        ya3 = fma2(d3, yrow[bg + 192], ya3);
    }
}

// Grid (c=256, btile=4). 512 threads: bg = tid&63 owns 4 b's; psplit = tid>>6
// owns 17 pairs. f32x2 lanes carry (even-i, odd-i) partial sums.
__global__ __launch_bounds__(512, 1)
void sc_main(const float* __restrict__ x, const float* __restrict__ y,
             float* __restrict__ out) {
    extern __shared__ char smraw[];
    float* sS3 = reinterpret_cast<float*>(smraw);
    float* sS2 = sS3 + S3_PER_C;
    float* sXs = sS2 + S2_PER_C;
    ull*   sYd = reinterpret_cast<ull*>(sXs + 256 * 17);
    int*   sPW = reinterpret_cast<int*>(sYd + EDIM * 256);
    int*   sPV = sPW + NPAIR;
    int*   sOF = sPV + NPAIR;
    float* red = reinterpret_cast<float*>(sOF + NPAIR);
    const ull* sS3u = reinterpret_cast<const ull*>(sS3);

    const int tid    = threadIdx.x;
    const int c      = blockIdx.x;
    const int base   = blockIdx.y * 256;
    const int bg     = tid & 63;
    const int psplit = tid >> 6;

    // ---- stage S3 / S2 (coalesced) ----
    {
        const float4* src = reinterpret_cast<const float4*>(S3g + c * S3_PER_C);
        float4* dst = reinterpret_cast<float4*>(sS3);
        for (int t = tid; t < S3_PER_C / 4; t += 512) dst[t] = src[t];
        for (int t = tid; t < S2_PER_C; t += 512) sS2[t] = S2g[c * S2_PER_C + t];
    }
    // ---- stage x scalars ----
#pragma unroll
    for (int t = 0; t < 8; t++) {
        const int idx = tid + t * 512;            // 4096 = 256*16
        const int b = idx >> 4, i = idx & 15;
        sXs[b * 17 + i] = x[((base + b) * CDIM + c) * LDIM + i];
    }
    // ---- stage dup'd y pairs [e][b] ----
#pragma unroll
    for (int t = 0; t < 5; t++) {
        const int idx = tid + t * 512;            // 2560 = 10*256
        const int b = idx & 255, e = idx >> 8;
        const float yv = y[(base + b) * EDIM + e];
        sYd[e * 256 + b] = pk2(yv, yv);
    }
    // ---- stage tables ----
    if (tid < NPAIR) {
        sPW[tid] = g_pw[tid];
        sPV[tid] = g_pv[tid];
        sOF[tid] = g_off[tid];
    }
    __syncthreads();

    // ---- per-thread packed x (4 b's) ----
    const int b0 = bg, b1 = bg + 64, b2 = bg + 128, b3 = bg + 192;
    ull xp0[8], xp1[8], xp2[8], xp3[8];
#pragma unroll
    for (int q = 0; q < 8; q++) {
        xp0[q] = pk2(sXs[b0 * 17 + 2 * q], sXs[b0 * 17 + 2 * q + 1]);
        xp1[q] = pk2(sXs[b1 * 17 + 2 * q], sXs[b1 * 17 + 2 * q + 1]);
        xp2[q] = pk2(sXs[b2 * 17 + 2 * q], sXs[b2 * 17 + 2 * q + 1]);
        xp3[q] = pk2(sXs[b3 * 17 + 2 * q], sXs[b3 * 17 + 2 * q + 1]);
    }

    ull acc0 = 0ull, acc1 = 0ull, acc2 = 0ull, acc3 = 0ull;

#pragma unroll 1
    for (int j = 0; j < 17; j++) {
        const int p = psplit * 17 + j;
        const int w = sPW[p], v = sPV[p], off = sOF[p];
        const float P0 = sXs[b0 * 17 + w] * sXs[b0 * 17 + v];
        const float P1 = sXs[b1 * 17 + w] * sXs[b1 * 17 + v];
        const float P2 = sXs[b2 * 17 + w] * sXs[b2 * 17 + v];
        const float P3 = sXs[b3 * 17 + w] * sXs[b3 * 17 + v];
        ull ya0 = 0ull, ya1 = 0ull, ya2 = 0ull, ya3 = 0ull;
        switch (8 - (v >> 1)) {
            case 8: dot_block<8>(sS3u, off, sS2, sYd, p, bg, xp0, xp1, xp2, xp3, ya0, ya1, ya2, ya3); break;
            case 7: dot_block<7>(sS3u, off, sS2, sYd, p, bg, xp0, xp1, xp2, xp3, ya0, ya1, ya2, ya3); break;
            case 6: dot_block<6>(sS3u, off, sS2, sYd, p, bg, xp0, xp1, xp2, xp3, ya0, ya1, ya2, ya3); break;
            case 5: dot_block<5>(sS3u, off, sS2, sYd, p, bg, xp0, xp1, xp2, xp3, ya0, ya1, ya2, ya3); break;
            case 4: dot_block<4>(sS3u, off, sS2, sYd, p, bg, xp0, xp1, xp2, xp3, ya0, ya1, ya2, ya3); break;
            case 3: dot_block<3>(sS3u, off, sS2, sYd, p, bg, xp0, xp1, xp2, xp3, ya0, ya1, ya2, ya3); break;
            case 2: dot_block<2>(sS3u, off, sS2, sYd, p, bg, xp0, xp1, xp2, xp3, ya0, ya1, ya2, ya3); break;
            default: dot_block<1>(sS3u, off, sS2, sYd, p, bg, xp0, xp1, xp2, xp3, ya0, ya1, ya2, ya3); break;
        }
        acc0 = fma2(pk2(P0, P0), ya0, acc0);
        acc1 = fma2(pk2(P1, P1), ya1, acc1);
        acc2 = fma2(pk2(P2, P2), ya2, acc2);
        acc3 = fma2(pk2(P3, P3), ya3, acc3);
    }

    float lo, hi;
    float s0, s1, s2, s3;
    upk2(acc0, lo, hi); s0 = lo + hi;
    upk2(acc1, lo, hi); s1 = lo + hi;
    upk2(acc2, lo, hi); s2 = lo + hi;
    upk2(acc3, lo, hi); s3 = lo + hi;

    // ---- nu=1 (psplit 0 only; warp-uniform) ----
    if (psplit == 0) {
        const float* v1 = V1g + c * V1_PER_C;
        float add[4] = {0.f, 0.f, 0.f, 0.f};
#pragma unroll 1
        for (int e = 0; e < EDIM; e++) {
            float t0 = 0.f, t1 = 0.f, t2 = 0.f, t3 = 0.f;
#pragma unroll
            for (int w = 0; w < 16; w++) {
                const float vv = v1[e * 16 + w];
                t0 = fmaf(vv, sXs[b0 * 17 + w], t0);
                t1 = fmaf(vv, sXs[b1 * 17 + w], t1);
                t2 = fmaf(vv, sXs[b2 * 17 + w], t2);
                t3 = fmaf(vv, sXs[b3 * 17 + w], t3);
            }
            add[0] = fmaf(y[(base + b0) * EDIM + e], t0, add[0]);
            add[1] = fmaf(y[(base + b1) * EDIM + e], t1, add[1]);
            add[2] = fmaf(y[(base + b2) * EDIM + e], t2, add[2]);
            add[3] = fmaf(y[(base + b3) * EDIM + e], t3, add[3]);
        }
        s0 += add[0]; s1 += add[1]; s2 += add[2]; s3 += add[3];
    }

    // ---- deterministic cross-split reduction ----
    red[psplit * 256 + b0] = s0;
    red[psplit * 256 + b1] = s1;
    red[psplit * 256 + b2] = s2;
    red[psplit * 256 + b3] = s3;
    __syncthreads();
    if (tid < 256) {
        float s = 0.f;
#pragma unroll
        for (int k = 0; k < 8; k++) s += red[k * 256 + tid];
        out[(base + tid) * CDIM + c] = s;
    }
}

// ---- launch -------------------------------------------------------------------
extern "C" void kernel_launch(void* const* d_in, const int* in_sizes, int n_in,
                              void* d_out, int out_size) {
    const float* x  = (const float*)d_in[0];
    const float* y  = (const float*)d_in[1];
    const float* U3 = (const float*)d_in[2];
    const float* U2 = (const float*)d_in[3];
    const float* U1 = (const float*)d_in[4];
    const float* W3 = (const float*)d_in[5];
    const float* W2 = (const float*)d_in[6];
    const float* W1 = (const float*)d_in[7];
    float* out = (float*)d_out;

    cudaFuncSetAttribute(k_s3, cudaFuncAttributeMaxDynamicSharedMemorySize, SMEM_KS3);
    cudaFuncSetAttribute(sc_main, cudaFuncAttributeMaxDynamicSharedMemorySize, SMEM_MAIN);

    k_tab<<<1, 1>>>();
    k_sym<<<(NSLOT_F * K3C + 255) / 256, 256>>>(U3);
    k_s3<<<CDIM, 512, SMEM_KS3>>>(W3);
    k_s2<<<(CDIM * S2_PER_C + 255) / 256, 256>>>(U2, W2);
    k_v1<<<(CDIM * V1_PER_C) / 256, 256>>>(U1, W1);

    dim3 grid(CDIM, BDIM / 256);
    sc_main<<<grid, 512, SMEM_MAIN>>>(x, y, out);
}